// round 1
// baseline (speedup 1.0000x reference)
#include <cuda_runtime.h>

#define TOP_K       200
#define CONF_THRESH 0.01f
#define NMS_THRESH  0.45f
#define BATCH       8
#define NPRI        4096
#define NTHREADS    512

__global__ void __launch_bounds__(NTHREADS)
post_rois_kernel(const float* __restrict__ loc,
                 const float* __restrict__ conf,
                 const float* __restrict__ prior,
                 float* __restrict__ out)
{
    __shared__ unsigned long long keys[NPRI];           // 32 KB
    __shared__ float kx1[TOP_K], ky1[TOP_K], kx2[TOP_K], ky2[TOP_K], karea[TOP_K];

    const int b   = blockIdx.x;
    const int tid = threadIdx.x;

    // Zero this image's output slice: (2 classes, TOP_K, 5)
    float* ob = out + (size_t)b * 2 * TOP_K * 5;
    for (int i = tid; i < 2 * TOP_K * 5; i += NTHREADS) ob[i] = 0.0f;

    // ---- Phase 1: scores -> sort keys (descending score, stable by index) ----
    for (int i = tid; i < NPRI; i += NTHREADS) {
        const float2 c = ((const float2*)conf)[(size_t)b * NPRI + i];
        float m  = fmaxf(c.x, c.y);
        float e0 = expf(c.x - m);
        float e1 = expf(c.y - m);
        float s  = e1 / (e0 + e1);               // softmax prob of class 1, in (0,1)
        // positive float -> bit pattern is order-monotonic; ~i => smaller index wins ties
        keys[i] = ((unsigned long long)__float_as_uint(s) << 32)
                | (unsigned long long)(0xFFFFFFFFu - (unsigned)i);
    }

    // ---- Phase 2: bitonic sort, descending ----
    for (int k = 2; k <= NPRI; k <<= 1) {
        for (int j = k >> 1; j > 0; j >>= 1) {
            __syncthreads();
            for (int i = tid; i < NPRI; i += NTHREADS) {
                int p = i ^ j;
                if (p > i) {
                    unsigned long long a = keys[i];
                    unsigned long long c = keys[p];
                    bool desc = ((i & k) == 0);
                    if (desc ? (a < c) : (a > c)) { keys[i] = c; keys[p] = a; }
                }
            }
        }
    }
    __syncthreads();

    // ---- Phase 3: greedy NMS on warp 0 ----
    if (tid >= 32) return;
    const int lane = tid;
    const float4* locb = (const float4*)(loc + (size_t)b * NPRI * 4);
    const float4* pri  = (const float4*)prior;

    int K = 0;
    for (int i = 0; i < NPRI && K < TOP_K; ++i) {
        const unsigned long long key = keys[i];
        const float sc = __uint_as_float((unsigned)(key >> 32));
        if (!(sc > CONF_THRESH)) break;          // sorted: valid region is a prefix
        const int idx = (int)(0xFFFFFFFFu - (unsigned)(key & 0xFFFFFFFFu));

        // Decode box (all lanes redundantly; L1-resident after first touch)
        const float4 l = locb[idx];
        const float4 p = pri[idx];
        const float cx = p.x + l.x * 0.1f * p.z;
        const float cy = p.y + l.y * 0.1f * p.w;
        const float w  = p.z * expf(l.z * 0.2f);
        const float h  = p.w * expf(l.w * 0.2f);
        const float x1 = cx - w * 0.5f, y1 = cy - h * 0.5f;
        const float x2 = cx + w * 0.5f, y2 = cy + h * 0.5f;
        const float area = (x2 - x1) * (y2 - y1);

        bool sup = false;
        for (int jj = lane; jj < K; jj += 32) {
            float iw = fminf(x2, kx2[jj]) - fmaxf(x1, kx1[jj]);
            float ih = fminf(y2, ky2[jj]) - fmaxf(y1, ky1[jj]);
            iw = fmaxf(iw, 0.0f);
            ih = fmaxf(ih, 0.0f);
            float inter = iw * ih;
            if (inter / (area + karea[jj] - inter) > NMS_THRESH) sup = true;
        }
        if (!__any_sync(0xffffffffu, sup)) {
            if (lane == 0) {
                kx1[K] = x1; ky1[K] = y1; kx2[K] = x2; ky2[K] = y2; karea[K] = area;
                float* o = ob + (size_t)(TOP_K + K) * 5;   // class 1 slice
                o[0] = sc; o[1] = x1; o[2] = y1; o[3] = x2; o[4] = y2;
            }
            __syncwarp();
            ++K;
        }
    }
}

extern "C" void kernel_launch(void* const* d_in, const int* in_sizes, int n_in,
                              void* d_out, int out_size)
{
    const float* loc   = (const float*)d_in[0];   // (8, 4096, 4) f32
    const float* conf  = (const float*)d_in[1];   // (32768, 2)   f32
    const float* prior = (const float*)d_in[2];   // (4096, 4)    f32
    float* out = (float*)d_out;                   // (8, 2, 200, 5) f32

    post_rois_kernel<<<BATCH, NTHREADS>>>(loc, conf, prior, out);
    (void)in_sizes; (void)n_in; (void)out_size;
}

// round 4
// speedup vs baseline: 3.6320x; 3.6320x over previous
#include <cuda_runtime.h>

#define TOP_K       200
#define CONF_THRESH 0.01f
#define NMS_THRESH  0.45f
#define BATCH       8
#define NPRI        4096
#define NTHREADS    512
#define GROUP       128
#define NW          (GROUP / 32)   // 4 mask words per candidate

__global__ void __launch_bounds__(NTHREADS)
post_rois_kernel(const float* __restrict__ loc,
                 const float* __restrict__ conf,
                 const float* __restrict__ prior,
                 float* __restrict__ out)
{
    __shared__ unsigned long long keys[NPRI];                        // 32 KB
    __shared__ float kx1[TOP_K], ky1[TOP_K], kx2[TOP_K], ky2[TOP_K], karea[TOP_K];
    __shared__ float gx1[GROUP], gy1[GROUP], gx2[GROUP], gy2[GROUP], garea[GROUP], gsc[GROUP];
    __shared__ uint4 gmask[GROUP];                                   // 128x128-bit masks
    __shared__ int   elig[GROUP];
    __shared__ unsigned keptw[NW];
    __shared__ int   K_sh, stop_sh;

    const int b   = blockIdx.x;
    const int tid = threadIdx.x;

    // Zero this image's output slice: (2 classes, TOP_K, 5)
    float* ob = out + (size_t)b * 2 * TOP_K * 5;
    for (int i = tid; i < 2 * TOP_K * 5; i += NTHREADS) ob[i] = 0.0f;

    // ---- Phase 1: scores -> sort keys (descending score, stable by index) ----
    for (int i = tid; i < NPRI; i += NTHREADS) {
        const float2 c = ((const float2*)conf)[(size_t)b * NPRI + i];
        float m  = fmaxf(c.x, c.y);
        float e0 = expf(c.x - m);
        float e1 = expf(c.y - m);
        float s  = e1 / (e0 + e1);               // softmax prob of class 1, in (0,1)
        keys[i] = ((unsigned long long)__float_as_uint(s) << 32)
                | (unsigned long long)(0xFFFFFFFFu - (unsigned)i);
    }

    // ---- Phase 2: bitonic sort, descending ----
    for (int k = 2; k <= NPRI; k <<= 1) {
        for (int j = k >> 1; j > 0; j >>= 1) {
            __syncthreads();
            for (int i = tid; i < NPRI; i += NTHREADS) {
                int p = i ^ j;
                if (p > i) {
                    unsigned long long a = keys[i];
                    unsigned long long c = keys[p];
                    bool desc = ((i & k) == 0);
                    if (desc ? (a < c) : (a > c)) { keys[i] = c; keys[p] = a; }
                }
            }
        }
    }

    // ---- Phase 3: batched greedy NMS (groups of 128, whole block) ----
    const float4* locb = (const float4*)(loc + (size_t)b * NPRI * 4);
    const float4* pri  = (const float4*)prior;

    if (tid == 0) { K_sh = 0; stop_sh = 0; }
    __syncthreads();

    int K = 0;
    for (int g0 = 0; g0 < NPRI; g0 += GROUP) {
        // Zero intra-group masks (512 words by 512 threads)
        ((unsigned*)gmask)[tid] = 0u;

        // Gather + decode the group's candidates in parallel
        if (tid < GROUP) {
            const unsigned long long key = keys[g0 + tid];
            const float sc  = __uint_as_float((unsigned)(key >> 32));
            const int   idx = (int)(0xFFFFFFFFu - (unsigned)(key & 0xFFFFFFFFu));
            const float4 l = locb[idx];
            const float4 p = pri[idx];
            const float cx = p.x + l.x * 0.1f * p.z;
            const float cy = p.y + l.y * 0.1f * p.w;
            const float w  = p.z * expf(l.z * 0.2f);
            const float h  = p.w * expf(l.w * 0.2f);
            const float x1 = cx - w * 0.5f, y1 = cy - h * 0.5f;
            const float x2 = cx + w * 0.5f, y2 = cy + h * 0.5f;
            gx1[tid] = x1; gy1[tid] = y1; gx2[tid] = x2; gy2[tid] = y2;
            garea[tid] = (x2 - x1) * (y2 - y1);
            gsc[tid]   = sc;
        }
        __syncthreads();

        // 4 threads per candidate
        const int c = tid >> 2, q = tid & 3;
        const float x1 = gx1[c], y1 = gy1[c], x2 = gx2[c], y2 = gy2[c], ar = garea[c];

        // (a) suppression vs already-kept boxes, strided over q
        int sup = 0;
        for (int j = q; j < K; j += 4) {
            float iw = fminf(x2, kx2[j]) - fmaxf(x1, kx1[j]);
            float ih = fminf(y2, ky2[j]) - fmaxf(y1, ky1[j]);
            iw = fmaxf(iw, 0.0f);
            ih = fmaxf(ih, 0.0f);
            float inter = iw * ih;
            if (inter / (ar + karea[j] - inter) > NMS_THRESH) sup = 1;
        }
        sup |= __shfl_xor_sync(0xffffffffu, sup, 1);
        sup |= __shfl_xor_sync(0xffffffffu, sup, 2);
        if (q == 0) elig[c] = (gsc[c] > CONF_THRESH) && !sup;

        // (b) intra-group pairwise mask: bits for earlier candidates j < c
        unsigned mw[NW] = {0u, 0u, 0u, 0u};
        #pragma unroll
        for (int s = 0; s < GROUP / 4; ++s) {
            const int j = q + 4 * s;
            if (j < c) {
                float iw = fminf(x2, gx2[j]) - fmaxf(x1, gx1[j]);
                float ih = fminf(y2, gy2[j]) - fmaxf(y1, gy1[j]);
                iw = fmaxf(iw, 0.0f);
                ih = fmaxf(ih, 0.0f);
                float inter = iw * ih;
                if (inter / (ar + garea[j] - inter) > NMS_THRESH)
                    mw[j >> 5] |= 1u << (j & 31);
            }
        }
        #pragma unroll
        for (int w = 0; w < NW; ++w)
            if (mw[w]) atomicOr(((unsigned*)&gmask[c]) + w, mw[w]);
        __syncthreads();

        // (c) serial greedy sweep over the group (one thread, register bitmasks)
        if (tid == 0) {
            unsigned kw[NW] = {0u, 0u, 0u, 0u};
            int Kl = 0;
            const int lim = TOP_K - K;
            #pragma unroll
            for (int w = 0; w < NW; ++w) {
                unsigned cur = 0u;
                for (int cb = 0; cb < 32; ++cb) {
                    if (Kl >= lim) break;
                    const int cc = w * 32 + cb;
                    if (!elig[cc]) continue;
                    const uint4 m = gmask[cc];
                    unsigned ov = (m.x & kw[0]) | (m.y & kw[1]) | (m.z & kw[2]) | (m.w & kw[3]);
                    ov |= ((w == 0) ? m.x : (w == 1) ? m.y : (w == 2) ? m.z : m.w) & cur;
                    if (ov) continue;
                    cur |= 1u << cb;
                    ++Kl;
                }
                kw[w] = cur;
            }
            keptw[0] = kw[0]; keptw[1] = kw[1]; keptw[2] = kw[2]; keptw[3] = kw[3];
            K_sh = K + Kl;
            stop_sh = !(gsc[GROUP - 1] > CONF_THRESH);   // boundary of valid prefix inside group
        }
        __syncthreads();

        // (d) parallel append of kept boxes + output rows
        if (tid < GROUP) {
            const int w = tid >> 5, bp = tid & 31;
            const unsigned word = keptw[w];
            if ((word >> bp) & 1u) {
                int pos = K;
                #pragma unroll
                for (int ww = 0; ww < NW; ++ww)
                    if (ww < w) pos += __popc(keptw[ww]);
                pos += __popc(word & ((1u << bp) - 1u));
                kx1[pos] = gx1[tid]; ky1[pos] = gy1[tid];
                kx2[pos] = gx2[tid]; ky2[pos] = gy2[tid];
                karea[pos] = garea[tid];
                float* o = ob + (size_t)(TOP_K + pos) * 5;   // class-1 slice
                o[0] = gsc[tid];
                o[1] = gx1[tid]; o[2] = gy1[tid]; o[3] = gx2[tid]; o[4] = gy2[tid];
            }
        }
        __syncthreads();

        K = K_sh;
        if (K >= TOP_K || stop_sh) break;
    }
}

extern "C" void kernel_launch(void* const* d_in, const int* in_sizes, int n_in,
                              void* d_out, int out_size)
{
    const float* loc   = (const float*)d_in[0];   // (8, 4096, 4) f32
    const float* conf  = (const float*)d_in[1];   // (32768, 2)   f32
    const float* prior = (const float*)d_in[2];   // (4096, 4)    f32
    float* out = (float*)d_out;                   // (8, 2, 200, 5) f32

    post_rois_kernel<<<BATCH, NTHREADS>>>(loc, conf, prior, out);
    (void)in_sizes; (void)n_in; (void)out_size;
}

// round 5
// speedup vs baseline: 6.7259x; 1.8518x over previous
#include <cuda_runtime.h>

#define TOP_K       200
#define CONF_THRESH 0.01f
#define NMS_THRESH  0.45f
#define BATCH       8
#define NPRI        4096
#define NT          1024
#define GROUP       128
#define NW          (GROUP / 32)   // 4 mask words per candidate

typedef unsigned long long u64;

__device__ __forceinline__ void cmpswap(u64& a, u64& b, bool desc) {
    if (desc ? (a < b) : (a > b)) { u64 t = a; a = b; b = t; }
}

__global__ void __launch_bounds__(NT)
post_rois_kernel(const float* __restrict__ loc,
                 const float* __restrict__ conf,
                 const float* __restrict__ prior,
                 float* __restrict__ out)
{
    __shared__ u64 keys[NPRI];                                       // 32 KB
    __shared__ float kx1[TOP_K], ky1[TOP_K], kx2[TOP_K], ky2[TOP_K], karea[TOP_K];
    __shared__ float gx1[GROUP], gy1[GROUP], gx2[GROUP], gy2[GROUP], garea[GROUP], gsc[GROUP];
    __shared__ uint4 gmask[GROUP];                                   // 128x128-bit intra masks
    __shared__ int   elig[GROUP];
    __shared__ unsigned keptw[NW];
    __shared__ int   K_sh, stop_sh;

    const int b   = blockIdx.x;
    const int tid = threadIdx.x;

    // Zero this image's output slice: (2 classes, TOP_K, 5)
    float* ob = out + (size_t)b * 2 * TOP_K * 5;
    for (int i = tid; i < 2 * TOP_K * 5; i += NT) ob[i] = 0.0f;

    // ---- Phase 1: scores -> sort keys (descending score, stable by index) ----
    for (int i = tid; i < NPRI; i += NT) {
        const float2 c = ((const float2*)conf)[(size_t)b * NPRI + i];
        float m  = fmaxf(c.x, c.y);
        float e0 = expf(c.x - m);
        float e1 = expf(c.y - m);
        float s  = e1 / (e0 + e1);               // softmax prob of class 1, in (0,1)
        keys[i] = ((u64)__float_as_uint(s) << 32)
                | (u64)(0xFFFFFFFFu - (unsigned)i);
    }
    __syncthreads();

    // ---- Phase 2: bitonic sort, descending; 4 keys/thread register-blocked ----
    const int base = tid * 4;
    {   // stages k=2 and k=4 entirely in registers
        u64 k0 = keys[base + 0], k1 = keys[base + 1];
        u64 k2 = keys[base + 2], k3 = keys[base + 3];
        cmpswap(k0, k1, true);                    // k=2: (i&2)==0
        cmpswap(k2, k3, false);                   // k=2: (i&2)!=0
        const bool d4 = ((base & 4) == 0);        // k=4 direction
        cmpswap(k0, k2, d4); cmpswap(k1, k3, d4);
        cmpswap(k0, k1, d4); cmpswap(k2, k3, d4);
        keys[base + 0] = k0; keys[base + 1] = k1;
        keys[base + 2] = k2; keys[base + 3] = k3;
    }
    for (int k = 8; k <= NPRI; k <<= 1) {
        for (int j = k >> 1; j >= 4; j >>= 1) {
            __syncthreads();
            for (int m = tid; m < NPRI / 2; m += NT) {
                const int i = ((m & ~(j - 1)) << 1) | (m & (j - 1));
                const int p = i | j;
                u64 a = keys[i], c = keys[p];
                const bool desc = ((i & k) == 0);
                if (desc ? (a < c) : (a > c)) { keys[i] = c; keys[p] = a; }
            }
        }
        __syncthreads();
        {   // fused j=2,1 tail in registers
            u64 k0 = keys[base + 0], k1 = keys[base + 1];
            u64 k2 = keys[base + 2], k3 = keys[base + 3];
            const bool d = ((base & k) == 0);
            cmpswap(k0, k2, d); cmpswap(k1, k3, d);
            cmpswap(k0, k1, d); cmpswap(k2, k3, d);
            keys[base + 0] = k0; keys[base + 1] = k1;
            keys[base + 2] = k2; keys[base + 3] = k3;
        }
    }
    __syncthreads();

    // ---- Phase 3: batched greedy NMS (groups of 128, whole block) ----
    const float4* locb = (const float4*)(loc + (size_t)b * NPRI * 4);
    const float4* pri  = (const float4*)prior;

    if (tid == 0) { K_sh = 0; stop_sh = 0; }
    __syncthreads();

    int K = 0;
    for (int g0 = 0; g0 < NPRI; g0 += GROUP) {
        // Gather + decode the group's candidates in parallel
        if (tid < GROUP) {
            const u64 key = keys[g0 + tid];
            const float sc  = __uint_as_float((unsigned)(key >> 32));
            const int   idx = (int)(0xFFFFFFFFu - (unsigned)(key & 0xFFFFFFFFu));
            const float4 l = locb[idx];
            const float4 p = pri[idx];
            const float cx = p.x + l.x * 0.1f * p.z;
            const float cy = p.y + l.y * 0.1f * p.w;
            const float w  = p.z * expf(l.z * 0.2f);
            const float h  = p.w * expf(l.w * 0.2f);
            const float x1 = cx - w * 0.5f, y1 = cy - h * 0.5f;
            const float x2 = cx + w * 0.5f, y2 = cy + h * 0.5f;
            gx1[tid] = x1; gy1[tid] = y1; gx2[tid] = x2; gy2[tid] = y2;
            garea[tid] = (x2 - x1) * (y2 - y1);
            gsc[tid]   = sc;
        }
        __syncthreads();

        // 8 threads per candidate
        const int c = tid >> 3, q = tid & 7;
        const float x1 = gx1[c], y1 = gy1[c], x2 = gx2[c], y2 = gy2[c], ar = garea[c];

        // (a) suppression vs already-kept boxes, strided over q
        int sup = 0;
        for (int j = q; j < K; j += 8) {
            float iw = fminf(x2, kx2[j]) - fmaxf(x1, kx1[j]);
            float ih = fminf(y2, ky2[j]) - fmaxf(y1, ky1[j]);
            iw = fmaxf(iw, 0.0f);
            ih = fmaxf(ih, 0.0f);
            float inter = iw * ih;
            if (inter / (ar + karea[j] - inter) > NMS_THRESH) sup = 1;
        }
        sup |= __shfl_xor_sync(0xffffffffu, sup, 1);
        sup |= __shfl_xor_sync(0xffffffffu, sup, 2);
        sup |= __shfl_xor_sync(0xffffffffu, sup, 4);

        // (b) intra-group pairwise mask: bits for earlier candidates j < c
        unsigned mw0 = 0u, mw1 = 0u, mw2 = 0u, mw3 = 0u;
        #pragma unroll
        for (int s = 0; s < GROUP / 8; ++s) {
            const int j = q + 8 * s;
            if (j < c) {
                float iw = fminf(x2, gx2[j]) - fmaxf(x1, gx1[j]);
                float ih = fminf(y2, gy2[j]) - fmaxf(y1, gy1[j]);
                iw = fmaxf(iw, 0.0f);
                ih = fmaxf(ih, 0.0f);
                float inter = iw * ih;
                if (inter / (ar + garea[j] - inter) > NMS_THRESH) {
                    const unsigned bit = 1u << (j & 31);
                    if      (j < 32) mw0 |= bit;
                    else if (j < 64) mw1 |= bit;
                    else if (j < 96) mw2 |= bit;
                    else             mw3 |= bit;
                }
            }
        }
        #pragma unroll
        for (int d = 1; d <= 4; d <<= 1) {
            mw0 |= __shfl_xor_sync(0xffffffffu, mw0, d);
            mw1 |= __shfl_xor_sync(0xffffffffu, mw1, d);
            mw2 |= __shfl_xor_sync(0xffffffffu, mw2, d);
            mw3 |= __shfl_xor_sync(0xffffffffu, mw3, d);
        }
        if (q == 0) {
            gmask[c] = make_uint4(mw0, mw1, mw2, mw3);
            elig[c]  = (gsc[c] > CONF_THRESH) && !sup;
        }
        __syncthreads();

        // (c) serial greedy sweep over the group (one thread, register bitmasks)
        if (tid == 0) {
            unsigned kw0 = 0u, kw1 = 0u, kw2 = 0u, kw3 = 0u;
            int Kl = 0;
            const int lim = TOP_K - K;
            #pragma unroll 8
            for (int cb = 0; cb < 32; ++cb) {
                const uint4 m = gmask[cb];
                const unsigned ov = (m.x & kw0);
                const int keep = elig[cb] & (ov == 0u) & (Kl < lim);
                kw0 |= (unsigned)keep << cb;
                Kl  += keep;
            }
            #pragma unroll 8
            for (int cb = 0; cb < 32; ++cb) {
                const uint4 m = gmask[32 + cb];
                const unsigned ov = (m.x & kw0) | (m.y & kw1);
                const int keep = elig[32 + cb] & (ov == 0u) & (Kl < lim);
                kw1 |= (unsigned)keep << cb;
                Kl  += keep;
            }
            #pragma unroll 8
            for (int cb = 0; cb < 32; ++cb) {
                const uint4 m = gmask[64 + cb];
                const unsigned ov = (m.x & kw0) | (m.y & kw1) | (m.z & kw2);
                const int keep = elig[64 + cb] & (ov == 0u) & (Kl < lim);
                kw2 |= (unsigned)keep << cb;
                Kl  += keep;
            }
            #pragma unroll 8
            for (int cb = 0; cb < 32; ++cb) {
                const uint4 m = gmask[96 + cb];
                const unsigned ov = (m.x & kw0) | (m.y & kw1) | (m.z & kw2) | (m.w & kw3);
                const int keep = elig[96 + cb] & (ov == 0u) & (Kl < lim);
                kw3 |= (unsigned)keep << cb;
                Kl  += keep;
            }
            keptw[0] = kw0; keptw[1] = kw1; keptw[2] = kw2; keptw[3] = kw3;
            K_sh = K + Kl;
            stop_sh = !(gsc[GROUP - 1] > CONF_THRESH);   // valid prefix ends inside group
        }
        __syncthreads();

        // (d) parallel append of kept boxes + output rows
        if (tid < GROUP) {
            const int w = tid >> 5, bp = tid & 31;
            const unsigned word = keptw[w];
            if ((word >> bp) & 1u) {
                int pos = K;
                #pragma unroll
                for (int ww = 0; ww < NW; ++ww)
                    if (ww < w) pos += __popc(keptw[ww]);
                pos += __popc(word & ((1u << bp) - 1u));
                kx1[pos] = gx1[tid]; ky1[pos] = gy1[tid];
                kx2[pos] = gx2[tid]; ky2[pos] = gy2[tid];
                karea[pos] = garea[tid];
                float* o = ob + (size_t)(TOP_K + pos) * 5;   // class-1 slice
                o[0] = gsc[tid];
                o[1] = gx1[tid]; o[2] = gy1[tid]; o[3] = gx2[tid]; o[4] = gy2[tid];
            }
        }
        __syncthreads();

        K = K_sh;
        if (K >= TOP_K || stop_sh) break;
    }
}

extern "C" void kernel_launch(void* const* d_in, const int* in_sizes, int n_in,
                              void* d_out, int out_size)
{
    const float* loc   = (const float*)d_in[0];   // (8, 4096, 4) f32
    const float* conf  = (const float*)d_in[1];   // (32768, 2)   f32
    const float* prior = (const float*)d_in[2];   // (4096, 4)    f32
    float* out = (float*)d_out;                   // (8, 2, 200, 5) f32

    post_rois_kernel<<<BATCH, NT>>>(loc, conf, prior, out);
    (void)in_sizes; (void)n_in; (void)out_size;
}